// round 11
// baseline (speedup 1.0000x reference)
#include <cuda_runtime.h>
#include <cuda_bf16.h>

#define H        1024
#define NEXP     4
#define TPB      128                 // 4 warps; 32 rows/block, 4 threads/row
#define ROWS_B   (TPB / NEXP)        // 32
#define TILE_K   64
#define NTILE    (H / TILE_K)        // 16
#define TK4      (TILE_K / 4)        // 16 float4 per row-tile
#define XSTR     (TK4 + 1)           // 17 float4 stride -> conflict-free
#define WSTR     (H + 4)             // 1028 floats per w row -> bank-shifted
#define STAGES   4                   // 3 tiles in flight per warp

// dynamic smem: [ ws: 4*WSTR floats | xs: STAGES * ROWS_B * XSTR float4 ]
#define WS_FLOATS (NEXP * WSTR)
#define SMEM_BYTES (WS_FLOATS * 4 + STAGES * ROWS_B * XSTR * 16)

__device__ __forceinline__ void issue_tile(const float* __restrict__ xblk,
                                           float4* __restrict__ xslot,
                                           int wi, int lane, int t)
{
    // warp wi stages rows [8wi, 8wi+8), TILE_K floats each:
    // 16 lanes x 16B = 256B contiguous per row, 2 rows per iteration.
    const int rp = lane >> 4;          // 0..1
    const int c  = lane & 15;          // float4 column 0..15
    const float* src0 = xblk + t * TILE_K + c * 4;
#pragma unroll
    for (int it = 0; it < 4; it++) {
        int r = wi * 8 + it * 2 + rp;
        const float* src = src0 + (size_t)r * H;
        float4* dst = xslot + r * XSTR + c;
        unsigned sa = (unsigned)__cvta_generic_to_shared(dst);
        asm volatile("cp.async.cg.shared.global [%0], [%1], 16;" :: "r"(sa), "l"(src));
    }
}

__global__ __launch_bounds__(TPB) void moe_gate_kernel(
    const float* __restrict__ x,      // [N, 1024]
    const float* __restrict__ w,      // [4, 1024]
    float* __restrict__ out,          // [2N idx | 2N wgt | 1 aux] fp32
    int nrows)
{
    extern __shared__ float smemf[];
    float*  ws = smemf;                               // padded natural w
    float4* xs = reinterpret_cast<float4*>(smemf + WS_FLOATS);

    const int tid  = threadIdx.x;
    const int wi   = tid >> 5;
    const int lane = tid & 31;
    const int rib  = tid >> 2;          // row in block 0..31
    const int e    = tid & 3;           // expert 0..3
    const float* xblk = x + (size_t)blockIdx.x * ROWS_B * H;

    // prologue: per-warp, issue first STAGES-1 tiles
#pragma unroll
    for (int p = 0; p < STAGES - 1; p++) {
        issue_tile(xblk, xs + p * (ROWS_B * XSTR), wi, lane, p);
        asm volatile("cp.async.commit_group;" ::: "memory");
    }

    // stage w into smem, padded rows (bank-shift 4 per expert)
    for (int i = tid; i < NEXP * H; i += TPB)
        ws[(i >> 10) * WSTR + (i & (H - 1))] = w[i];
    __syncthreads();                    // only block-wide sync (ws ready)

    const float* wrow = ws + e * WSTR;  // this thread's expert row

    float acc = 0.0f;                   // ONE serial ascending fmaf chain
    for (int t = 0; t < NTILE; t++) {
        asm volatile("cp.async.wait_group 2;" ::: "memory");
        __syncwarp();                   // lane-mates' staged rows visible

        const float4* xr = xs + (t & (STAGES - 1)) * (ROWS_B * XSTR) + rib * XSTR;
        const float4* we = reinterpret_cast<const float4*>(wrow + t * TILE_K);
#pragma unroll
        for (int k4 = 0; k4 < TK4; k4++) {
            float4 v  = xr[k4];         // 4-lane broadcast, conflict-free
            float4 wv = we[k4];         // 8-way broadcast, bank-shifted
            acc = fmaf(v.x, wv.x, acc); // strict serial ascending k chain
            acc = fmaf(v.y, wv.y, acc);
            acc = fmaf(v.z, wv.z, acc);
            acc = fmaf(v.w, wv.w, acc);
        }

        int tn = t + STAGES - 1;        // refill freed slot
        if (tn < NTILE)
            issue_tile(xblk, xs + (tn & (STAGES - 1)) * (ROWS_B * XSTR), wi, lane, tn);
        asm volatile("cp.async.commit_group;" ::: "memory");
    }

    // gather the 4 expert logits within each 4-lane row group
    const unsigned mask = 0xffffffffu;
    float lg[NEXP];
#pragma unroll
    for (int k = 0; k < NEXP; k++)
        lg[k] = __shfl_sync(mask, acc, k, 4);

    const size_t row = (size_t)blockIdx.x * ROWS_B + rib;
    if (e == 0 && row < (size_t)nrows) {
        float m = lg[0];
        #pragma unroll
        for (int k = 1; k < NEXP; k++) m = fmaxf(m, lg[k]);

        // Frozen reference-softmax contract (R5/R8): accurate exp,
        // sequential fp32 sum, rn division, flush denormal scores to 0.
        float q[NEXP];
        #pragma unroll
        for (int k = 0; k < NEXP; k++)
            q[k] = (float)exp((double)(lg[k] - m));
        float sum = ((q[0] + q[1]) + q[2]) + q[3];

        unsigned kb[NEXP];
        float sc[NEXP];
        #pragma unroll
        for (int k = 0; k < NEXP; k++) {
            float s = __fdiv_rn(q[k], sum);
            unsigned b = __float_as_uint(s);
            if (b < 0x00800000u) { b = 0u; s = 0.0f; }
            kb[k] = b; sc[k] = s;
        }

        int i0 = 0;
        #pragma unroll
        for (int k = 1; k < NEXP; k++) if (kb[k] > kb[i0]) i0 = k;
        int i1 = -1;
        #pragma unroll
        for (int k = 0; k < NEXP; k++) {
            if (k == i0) continue;
            if (i1 < 0 || kb[k] > kb[i1]) i1 = k;
        }

        float2* oidx = reinterpret_cast<float2*>(out);
        float2* owgt = reinterpret_cast<float2*>(out + 2 * (size_t)nrows);
        oidx[row] = make_float2((float)i0, (float)i1);
        owgt[row] = make_float2(sc[i0], sc[i1]);

        if (row == 0)
            out[4 * (size_t)nrows] = 0.01f;   // aux_loss == ALPHA analytically
    }
}

extern "C" void kernel_launch(void* const* d_in, const int* in_sizes, int n_in,
                              void* d_out, int out_size)
{
    const float* x = (const float*)d_in[0];   // hidden_states [8,4096,1024] fp32
    const float* w = (const float*)d_in[1];   // weight [4,1024] fp32
    float* out = (float*)d_out;

    int nrows = in_sizes[0] / H;              // 32768
    int blocks = (nrows + ROWS_B - 1) / ROWS_B;   // 1024

    cudaFuncSetAttribute(moe_gate_kernel,
                         cudaFuncAttributeMaxDynamicSharedMemorySize, SMEM_BYTES);
    moe_gate_kernel<<<blocks, TPB, SMEM_BYTES>>>(x, w, out, nrows);
}

// round 12
// speedup vs baseline: 1.0571x; 1.0571x over previous
#include <cuda_runtime.h>
#include <cuda_bf16.h>

#define H        1024
#define NEXP     4
#define TPB      128                 // 4 warps; 2 threads/row -> 64 rows/block
#define ROWS_B   (TPB / 2)           // 64
#define ROWS_W   16                  // rows per warp
#define TILE_K   32
#define NTILE    (H / TILE_K)        // 32
#define TK4      (TILE_K / 4)        // 8 float4 per row-tile
#define XSTR     (TK4 + 1)           // 9 float4 stride -> conflict-free LDS.128
#define WSTR     (H + 4)             // bank-shifted w rows
#define STAGES   5                   // 4 tiles in flight per warp

#define WS_FLOATS (NEXP * WSTR)
#define XS_F4     (ROWS_B * XSTR)    // float4 per stage
#define SMEM_BYTES (WS_FLOATS * 4 + STAGES * XS_F4 * 16)

__device__ __forceinline__ void issue_tile(const float* __restrict__ xblk,
                                           float4* __restrict__ xslot,
                                           int wi, int lane, int t)
{
    // warp wi stages rows [16wi, 16wi+16), TILE_K floats each.
    // per iter: lanes cover 4 rows x 8 float4 = 4 contiguous 128B segments.
#pragma unroll
    for (int it = 0; it < 4; it++) {
        int idx = it * 32 + lane;          // 0..127
        int rl  = idx >> 3;                // row-local 0..15
        int c   = idx & 7;                 // float4 col 0..7
        const float* src = xblk + (size_t)(wi * ROWS_W + rl) * H + t * TILE_K + c * 4;
        float4* dst = xslot + (wi * ROWS_W + rl) * XSTR + c;
        unsigned sa = (unsigned)__cvta_generic_to_shared(dst);
        asm volatile("cp.async.cg.shared.global [%0], [%1], 16;" :: "r"(sa), "l"(src));
    }
}

__global__ __launch_bounds__(TPB) void moe_gate_kernel(
    const float* __restrict__ x,      // [N, 1024]
    const float* __restrict__ w,      // [4, 1024]
    float* __restrict__ out,          // [2N idx | 2N wgt | 1 aux] fp32
    int nrows)
{
    extern __shared__ float smemf[];
    float*  ws = smemf;                               // 4 padded w rows
    float4* xs = reinterpret_cast<float4*>(smemf + WS_FLOATS);

    const int tid  = threadIdx.x;
    const int wi   = tid >> 5;
    const int lane = tid & 31;
    const int p    = lane & 1;         // expert pair: {0,1} or {2,3}
    const int rw   = lane >> 1;        // row-in-warp 0..15
    const float* xblk = x + (size_t)blockIdx.x * ROWS_B * H;

    // prologue: per-warp, issue first STAGES-1 tiles
#pragma unroll
    for (int s = 0; s < STAGES - 1; s++) {
        issue_tile(xblk, xs + s * XS_F4, wi, lane, s);
        asm volatile("cp.async.commit_group;" ::: "memory");
    }

    // stage w (padded rows), only block-wide dependency
    for (int i = tid; i < NEXP * H; i += TPB)
        ws[(i >> 10) * WSTR + (i & (H - 1))] = w[i];
    __syncthreads();

    const float* wra = ws + (2 * p + 0) * WSTR;
    const float* wrb = ws + (2 * p + 1) * WSTR;

    float acc0 = 0.f, acc1 = 0.f;      // two serial ascending chains (ILP 2)

    for (int t = 0; t < NTILE; t++) {
        asm volatile("cp.async.wait_group %0;" :: "n"(STAGES - 2) : "memory");
        __syncwarp();

        const float4* xr = xs + (t % STAGES) * XS_F4 + (wi * ROWS_W + rw) * XSTR;
        const float4* wa = reinterpret_cast<const float4*>(wra + t * TILE_K);
        const float4* wb = reinterpret_cast<const float4*>(wrb + t * TILE_K);
#pragma unroll
        for (int k4 = 0; k4 < TK4; k4++) {
            float4 v  = xr[k4];            // 2-lane bcast, conflict-free (pad 9)
            float4 va = wa[k4];            // 16-lane broadcast
            float4 vb = wb[k4];
            acc0 = fmaf(v.x, va.x, acc0);  acc1 = fmaf(v.x, vb.x, acc1);
            acc0 = fmaf(v.y, va.y, acc0);  acc1 = fmaf(v.y, vb.y, acc1);
            acc0 = fmaf(v.z, va.z, acc0);  acc1 = fmaf(v.z, vb.z, acc1);
            acc0 = fmaf(v.w, va.w, acc0);  acc1 = fmaf(v.w, vb.w, acc1);
        }

        int tn = t + STAGES - 1;           // refill freed slot
        if (tn < NTILE)
            issue_tile(xblk, xs + (tn % STAGES) * XS_F4, wi, lane, tn);
        asm volatile("cp.async.commit_group;" ::: "memory");
    }

    // gather 4 logits within each 2-lane pair: even lane has e0,e1; odd e2,e3
    const unsigned mask = 0xffffffffu;
    float lg[NEXP];
    lg[0] = __shfl_sync(mask, acc0, 0, 2);
    lg[1] = __shfl_sync(mask, acc1, 0, 2);
    lg[2] = __shfl_sync(mask, acc0, 1, 2);
    lg[3] = __shfl_sync(mask, acc1, 1, 2);

    const size_t row = (size_t)blockIdx.x * ROWS_B + wi * ROWS_W + rw;
    if (p == 0 && row < (size_t)nrows) {
        float m = lg[0];
        #pragma unroll
        for (int k = 1; k < NEXP; k++) m = fmaxf(m, lg[k]);

        // Frozen reference-softmax contract (R5/R8): accurate exp,
        // sequential fp32 sum, rn division, flush denormal scores to 0.
        float q[NEXP];
        #pragma unroll
        for (int k = 0; k < NEXP; k++)
            q[k] = (float)exp((double)(lg[k] - m));
        float sum = ((q[0] + q[1]) + q[2]) + q[3];

        unsigned kb[NEXP];
        float sc[NEXP];
        #pragma unroll
        for (int k = 0; k < NEXP; k++) {
            float s = __fdiv_rn(q[k], sum);
            unsigned b = __float_as_uint(s);
            if (b < 0x00800000u) { b = 0u; s = 0.0f; }
            kb[k] = b; sc[k] = s;
        }

        int i0 = 0;
        #pragma unroll
        for (int k = 1; k < NEXP; k++) if (kb[k] > kb[i0]) i0 = k;
        int i1 = -1;
        #pragma unroll
        for (int k = 0; k < NEXP; k++) {
            if (k == i0) continue;
            if (i1 < 0 || kb[k] > kb[i1]) i1 = k;
        }

        float2* oidx = reinterpret_cast<float2*>(out);
        float2* owgt = reinterpret_cast<float2*>(out + 2 * (size_t)nrows);
        oidx[row] = make_float2((float)i0, (float)i1);
        owgt[row] = make_float2(sc[i0], sc[i1]);

        if (row == 0)
            out[4 * (size_t)nrows] = 0.01f;   // aux_loss == ALPHA analytically
    }
}

extern "C" void kernel_launch(void* const* d_in, const int* in_sizes, int n_in,
                              void* d_out, int out_size)
{
    const float* x = (const float*)d_in[0];   // hidden_states [8,4096,1024] fp32
    const float* w = (const float*)d_in[1];   // weight [4,1024] fp32
    float* out = (float*)d_out;

    int nrows = in_sizes[0] / H;              // 32768
    int blocks = (nrows + ROWS_B - 1) / ROWS_B;   // 512

    cudaFuncSetAttribute(moe_gate_kernel,
                         cudaFuncAttributeMaxDynamicSharedMemorySize, SMEM_BYTES);
    moe_gate_kernel<<<blocks, TPB, SMEM_BYTES>>>(x, w, out, nrows);
}

// round 13
// speedup vs baseline: 1.4282x; 1.3511x over previous
#include <cuda_runtime.h>
#include <cuda_bf16.h>

#define H        1024
#define NEXP     4
#define TPB      64                  // 2 warps; 1 thread per row -> 64 rows/block
#define ROWS_B   TPB
#define TILE_K   32
#define NTILE    (H / TILE_K)        // 32
#define TK4      (TILE_K / 4)        // 8 float4 per row-tile
#define XSTR     (TK4 + 1)           // 9 float4 stride -> conflict-free LDS.128
#define STAGES   4                   // 3 tiles in flight per warp

#define XS_F4    (ROWS_B * XSTR)     // float4 per stage (576)
// dynamic smem: [ wt: H float4 | xs: STAGES * XS_F4 float4 ]  = 52 KB
#define SMEM_BYTES ((H + STAGES * XS_F4) * (int)sizeof(float4))

__device__ __forceinline__ void issue_tile(const float* __restrict__ xblk,
                                           float4* __restrict__ xslot,
                                           int wi, int lane, int t)
{
    // warp wi stages rows [32wi, 32wi+32), TILE_K floats each.
    // per iter: 4 rows x 8 lanes x 16B = 4 contiguous 128B segments.
    const int rr = lane >> 3;      // 0..3 row-in-group
    const int c  = lane & 7;       // 0..7 float4 column
    const float* src0 = xblk + t * TILE_K + c * 4;
#pragma unroll
    for (int it = 0; it < 8; it++) {
        int r = wi * 32 + it * 4 + rr;
        const float* src = src0 + (size_t)r * H;
        float4* dst = xslot + r * XSTR + c;
        unsigned sa = (unsigned)__cvta_generic_to_shared(dst);
        asm volatile("cp.async.cg.shared.global [%0], [%1], 16;" :: "r"(sa), "l"(src));
    }
}

__global__ __launch_bounds__(TPB) void moe_gate_kernel(
    const float* __restrict__ x,      // [N, 1024]
    const float* __restrict__ w,      // [4, 1024]
    float* __restrict__ out,          // [2N idx | 2N wgt | 1 aux] fp32
    int nrows)
{
    extern __shared__ float4 smem[];
    float4* wt = smem;                          // wt[k] = {w0,w1,w2,w3}[k]
    float4* xs = smem + H;

    const int tid  = threadIdx.x;
    const int wi   = tid >> 5;
    const int lane = tid & 31;
    const float* xblk = x + (size_t)blockIdx.x * ROWS_B * H;

    // prologue: per-warp, issue first STAGES-1 tiles
#pragma unroll
    for (int p = 0; p < STAGES - 1; p++) {
        issue_tile(xblk, xs + p * XS_F4, wi, lane, p);
        asm volatile("cp.async.commit_group;" ::: "memory");
    }

    // weight transpose into smem (only block-wide dependency)
    for (int k = tid; k < H; k += TPB)
        wt[k] = make_float4(w[k], w[H + k], w[2 * H + k], w[3 * H + k]);
    __syncthreads();

    float a0 = 0.f, a1 = 0.f, a2 = 0.f, a3 = 0.f;

    for (int t = 0; t < NTILE; t++) {
        asm volatile("cp.async.wait_group 2;" ::: "memory");
        __syncwarp();   // staged rows visible warp-wide

        const float4* xrow = xs + (t & (STAGES - 1)) * XS_F4 + tid * XSTR;
        const float4* wk   = wt + t * TILE_K;

        // ---- software-pipelined k4 loop: prefetch next v/w while FMAing ----
        float4 v  = xrow[0];
        float4 w0 = wk[0], w1 = wk[1], w2 = wk[2], w3 = wk[3];
#pragma unroll
        for (int k4 = 0; k4 < TK4; k4++) {
            float4 vn, w0n, w1n, w2n, w3n;
            if (k4 < TK4 - 1) {
                vn  = xrow[k4 + 1];
                w0n = wk[(k4 + 1) * 4 + 0];
                w1n = wk[(k4 + 1) * 4 + 1];
                w2n = wk[(k4 + 1) * 4 + 2];
                w3n = wk[(k4 + 1) * 4 + 3];
            }
            // 4 serial ascending chains (bit-exact contract)
            a0 = fmaf(v.x, w0.x, a0); a1 = fmaf(v.x, w0.y, a1);
            a2 = fmaf(v.x, w0.z, a2); a3 = fmaf(v.x, w0.w, a3);
            a0 = fmaf(v.y, w1.x, a0); a1 = fmaf(v.y, w1.y, a1);
            a2 = fmaf(v.y, w1.z, a2); a3 = fmaf(v.y, w1.w, a3);
            a0 = fmaf(v.z, w2.x, a0); a1 = fmaf(v.z, w2.y, a1);
            a2 = fmaf(v.z, w2.z, a2); a3 = fmaf(v.z, w2.w, a3);
            a0 = fmaf(v.w, w3.x, a0); a1 = fmaf(v.w, w3.y, a1);
            a2 = fmaf(v.w, w3.z, a2); a3 = fmaf(v.w, w3.w, a3);
            v = vn; w0 = w0n; w1 = w1n; w2 = w2n; w3 = w3n;
        }

        int tn = t + STAGES - 1;        // refill freed slot
        if (tn < NTILE)
            issue_tile(xblk, xs + (tn & (STAGES - 1)) * XS_F4, wi, lane, tn);
        asm volatile("cp.async.commit_group;" ::: "memory");
    }

    const size_t row = (size_t)blockIdx.x * ROWS_B + tid;
    if (row < (size_t)nrows) {
        float lg[NEXP] = {a0, a1, a2, a3};
        float m = lg[0];
        #pragma unroll
        for (int k = 1; k < NEXP; k++) m = fmaxf(m, lg[k]);

        // Frozen reference-softmax contract (R5/R8): accurate exp,
        // sequential fp32 sum, rn division, flush denormal scores to 0.
        float q[NEXP];
        #pragma unroll
        for (int k = 0; k < NEXP; k++)
            q[k] = (float)exp((double)(lg[k] - m));
        float sum = ((q[0] + q[1]) + q[2]) + q[3];

        unsigned kb[NEXP];
        float sc[NEXP];
        #pragma unroll
        for (int k = 0; k < NEXP; k++) {
            float s = __fdiv_rn(q[k], sum);
            unsigned b = __float_as_uint(s);
            if (b < 0x00800000u) { b = 0u; s = 0.0f; }
            kb[k] = b; sc[k] = s;
        }

        int i0 = 0;
        #pragma unroll
        for (int k = 1; k < NEXP; k++) if (kb[k] > kb[i0]) i0 = k;
        int i1 = -1;
        #pragma unroll
        for (int k = 0; k < NEXP; k++) {
            if (k == i0) continue;
            if (i1 < 0 || kb[k] > kb[i1]) i1 = k;
        }

        float2* oidx = reinterpret_cast<float2*>(out);
        float2* owgt = reinterpret_cast<float2*>(out + 2 * (size_t)nrows);
        oidx[row] = make_float2((float)i0, (float)i1);
        owgt[row] = make_float2(sc[i0], sc[i1]);

        if (row == 0)
            out[4 * (size_t)nrows] = 0.01f;   // aux_loss == ALPHA analytically
    }
}

extern "C" void kernel_launch(void* const* d_in, const int* in_sizes, int n_in,
                              void* d_out, int out_size)
{
    const float* x = (const float*)d_in[0];   // hidden_states [8,4096,1024] fp32
    const float* w = (const float*)d_in[1];   // weight [4,1024] fp32
    float* out = (float*)d_out;

    int nrows = in_sizes[0] / H;              // 32768
    int blocks = (nrows + ROWS_B - 1) / ROWS_B;   // 512 -> all resident, balanced

    cudaFuncSetAttribute(moe_gate_kernel,
                         cudaFuncAttributeMaxDynamicSharedMemorySize, SMEM_BYTES);
    moe_gate_kernel<<<blocks, TPB, SMEM_BYTES>>>(x, w, out, nrows);
}

// round 14
// speedup vs baseline: 1.4293x; 1.0008x over previous
#include <cuda_runtime.h>
#include <cuda_bf16.h>

#define H        1024
#define NEXP     4
#define TPB      128                 // warps 0,1 consumers; 2,3 producers
#define ROWS_B   64                  // rows per block (consumer lanes)
#define TILE_K   32
#define NTILE    (H / TILE_K)        // 32
#define TK4      (TILE_K / 4)        // 8
#define XSTR     (TK4 + 1)           // 9 -> conflict-free LDS.128
#define STAGES   4
#define XS_F4    (ROWS_B * XSTR)     // 576 float4 per stage

// smem: wt (H float4) | xs (STAGES*XS_F4 float4) | 16 mbarriers
#define SMEM_BYTES ((H + STAGES * XS_F4) * 16 + 128)

__device__ __forceinline__ unsigned smem_u32(const void* p) {
    return (unsigned)__cvta_generic_to_shared(p);
}
__device__ __forceinline__ void mbar_init(unsigned a, unsigned cnt) {
    asm volatile("mbarrier.init.shared.b64 [%0], %1;" :: "r"(a), "r"(cnt));
}
__device__ __forceinline__ void mbar_wait(unsigned a, unsigned parity) {
    asm volatile(
        "{\n\t.reg .pred P;\n\t"
        "WL%=:\n\t"
        "mbarrier.try_wait.parity.acquire.cta.shared::cta.b64 P, [%0], %1, 0x989680;\n\t"
        "@P bra WD%=;\n\t"
        "bra WL%=;\n\t"
        "WD%=:\n\t}"
        :: "r"(a), "r"(parity) : "memory");
}
__device__ __forceinline__ void mbar_arrive(unsigned a) {
    asm volatile("mbarrier.arrive.shared.b64 _, [%0];" :: "r"(a) : "memory");
}

__global__ __launch_bounds__(TPB) void moe_gate_kernel(
    const float* __restrict__ x,      // [N, 1024]
    const float* __restrict__ w,      // [4, 1024]
    float* __restrict__ out,          // [2N idx | 2N wgt | 1 aux] fp32
    int nrows)
{
    extern __shared__ float4 smem[];
    float4* wt = smem;                          // wt[k] = {w0,w1,w2,w3}[k]
    float4* xs = smem + H;                      // ring: STAGES x (64 rows x XSTR)
    unsigned bar0 = smem_u32(xs + STAGES * XS_F4);
    // full[p][s]  at bar0 + (p*STAGES+s)*8        (count 32: producer lanes)
    // empty[p][s] at bar0 + 64 + (p*STAGES+s)*8   (count 32: consumer lanes)

    const int tid  = threadIdx.x;
    const int wi   = tid >> 5;
    const int lane = tid & 31;
    const float* xblk = x + (size_t)blockIdx.x * ROWS_B * H;

    if (tid == 0) {
        for (int i = 0; i < 2 * STAGES; i++) {
            mbar_init(bar0 + i * 8, 32);        // full
            mbar_init(bar0 + 64 + i * 8, 32);   // empty
        }
    }
    // weight transpose into smem (cooperative, all warps)
    for (int k = tid; k < H; k += TPB)
        wt[k] = make_float4(w[k], w[H + k], w[2 * H + k], w[3 * H + k]);
    __syncthreads();   // barriers + wt visible before any async traffic

    if (wi >= 2) {
        // ================= PRODUCER (warp 2 -> pair 0, warp 3 -> pair 1) ====
        const int p = wi - 2;
        const unsigned fb = bar0 + (p * STAGES) * 8;
        const unsigned eb = bar0 + 64 + (p * STAGES) * 8;
        const float* xp = xblk + (size_t)p * 32 * H;
        const int rr = lane >> 3;          // 0..3 row-in-group
        const int c  = lane & 7;           // 0..7 float4 column

        for (int t = 0; t < NTILE; t++) {
            const int s = t & (STAGES - 1);
            if (t >= STAGES)
                mbar_wait(eb + s * 8, ((t >> 2) - 1) & 1);  // slot free?
            float4* slot = xs + s * XS_F4 + p * 32 * XSTR;
            const float* src0 = xp + t * TILE_K + c * 4;
#pragma unroll
            for (int it = 0; it < 8; it++) {
                int r = it * 4 + rr;
                unsigned d = smem_u32(slot + r * XSTR + c);
                asm volatile("cp.async.cg.shared.global [%0], [%1], 16;"
                             :: "r"(d), "l"(src0 + (size_t)r * H));
            }
            // arrive on full[s] when THIS thread's prior cp.asyncs complete
            asm volatile("cp.async.mbarrier.arrive.noinc.shared.b64 [%0];"
                         :: "r"(fb + s * 8) : "memory");
        }
        asm volatile("cp.async.wait_all;" ::: "memory");
    } else {
        // ================= CONSUMER (warp 0/1, lane = row-in-warp) ==========
        const int p = wi;
        const unsigned fb = bar0 + (p * STAGES) * 8;
        const unsigned eb = bar0 + 64 + (p * STAGES) * 8;
        const int rloc = wi * 32 + lane;

        float a0 = 0.f, a1 = 0.f, a2 = 0.f, a3 = 0.f;
        for (int t = 0; t < NTILE; t++) {
            const int s = t & (STAGES - 1);
            mbar_wait(fb + s * 8, (t >> 2) & 1);            // tile ready

            const float4* xrow = xs + s * XS_F4 + rloc * XSTR;
            const float4* wk   = wt + t * TILE_K;
#pragma unroll
            for (int k4 = 0; k4 < TK4; k4++) {
                float4 v  = xrow[k4];          // conflict-free via XSTR pad
                float4 w0 = wk[k4 * 4 + 0];    // warp-uniform broadcasts
                a0 = fmaf(v.x, w0.x, a0); a1 = fmaf(v.x, w0.y, a1);
                a2 = fmaf(v.x, w0.z, a2); a3 = fmaf(v.x, w0.w, a3);
                float4 w1 = wk[k4 * 4 + 1];
                a0 = fmaf(v.y, w1.x, a0); a1 = fmaf(v.y, w1.y, a1);
                a2 = fmaf(v.y, w1.z, a2); a3 = fmaf(v.y, w1.w, a3);
                float4 w2 = wk[k4 * 4 + 2];
                a0 = fmaf(v.z, w2.x, a0); a1 = fmaf(v.z, w2.y, a1);
                a2 = fmaf(v.z, w2.z, a2); a3 = fmaf(v.z, w2.w, a3);
                float4 w3 = wk[k4 * 4 + 3];
                a0 = fmaf(v.w, w3.x, a0); a1 = fmaf(v.w, w3.y, a1);
                a2 = fmaf(v.w, w3.z, a2); a3 = fmaf(v.w, w3.w, a3);
            }
            mbar_arrive(eb + s * 8);                        // slot consumed
        }

        const size_t row = (size_t)blockIdx.x * ROWS_B + rloc;
        if (row < (size_t)nrows) {
            float lg[NEXP] = {a0, a1, a2, a3};
            float m = lg[0];
            #pragma unroll
            for (int k = 1; k < NEXP; k++) m = fmaxf(m, lg[k]);

            // Frozen reference-softmax contract (R5/R8): accurate exp,
            // sequential fp32 sum, rn division, flush denormal scores to 0.
            float q[NEXP];
            #pragma unroll
            for (int k = 0; k < NEXP; k++)
                q[k] = (float)exp((double)(lg[k] - m));
            float sum = ((q[0] + q[1]) + q[2]) + q[3];

            unsigned kb[NEXP];
            float sc[NEXP];
            #pragma unroll
            for (int k = 0; k < NEXP; k++) {
                float s = __fdiv_rn(q[k], sum);
                unsigned b = __float_as_uint(s);
                if (b < 0x00800000u) { b = 0u; s = 0.0f; }
                kb[k] = b; sc[k] = s;
            }

            int i0 = 0;
            #pragma unroll
            for (int k = 1; k < NEXP; k++) if (kb[k] > kb[i0]) i0 = k;
            int i1 = -1;
            #pragma unroll
            for (int k = 0; k < NEXP; k++) {
                if (k == i0) continue;
                if (i1 < 0 || kb[k] > kb[i1]) i1 = k;
            }

            float2* oidx = reinterpret_cast<float2*>(out);
            float2* owgt = reinterpret_cast<float2*>(out + 2 * (size_t)nrows);
            oidx[row] = make_float2((float)i0, (float)i1);
            owgt[row] = make_float2(sc[i0], sc[i1]);

            if (row == 0)
                out[4 * (size_t)nrows] = 0.01f;  // aux_loss == ALPHA analytically
        }
    }
}

extern "C" void kernel_launch(void* const* d_in, const int* in_sizes, int n_in,
                              void* d_out, int out_size)
{
    const float* x = (const float*)d_in[0];   // hidden_states [8,4096,1024] fp32
    const float* w = (const float*)d_in[1];   // weight [4,1024] fp32
    float* out = (float*)d_out;

    int nrows = in_sizes[0] / H;              // 32768
    int blocks = (nrows + ROWS_B - 1) / ROWS_B;   // 512 -> all resident @4 CTA/SM

    cudaFuncSetAttribute(moe_gate_kernel,
                         cudaFuncAttributeMaxDynamicSharedMemorySize, SMEM_BYTES);
    moe_gate_kernel<<<blocks, TPB, SMEM_BYTES>>>(x, w, out, nrows);
}